// round 4
// baseline (speedup 1.0000x reference)
#include <cuda_runtime.h>
#include <cuda_bf16.h>
#include <math.h>

#define FNUM  32
#define BATCH 2048
#define KD    64
#define HD    64
#define NPAIR 496
#define NW    72     // 64 hid cols + 1 g col (=p) + 7 pad rows of zeros
#define VROW  68     // padded V row stride (floats)
#define WROW  72     // padded Wt row stride (bf16)

__device__ __forceinline__ unsigned smem_u32(const void* p) {
    return (unsigned)__cvta_generic_to_shared(p);
}

__device__ __forceinline__ unsigned cvt_bf16x2(float hi, float lo) {
    unsigned r;
    asm("cvt.rn.bf16x2.f32 %0, %1, %2;" : "=r"(r) : "f"(hi), "f"(lo));
    return r;
}

__device__ __forceinline__ void ldmatrix_x4(unsigned& r0, unsigned& r1, unsigned& r2, unsigned& r3,
                                            unsigned addr) {
    asm volatile("ldmatrix.sync.aligned.m8n8.x4.shared.b16 {%0,%1,%2,%3}, [%4];"
                 : "=r"(r0), "=r"(r1), "=r"(r2), "=r"(r3) : "r"(addr));
}

__device__ __forceinline__ void mma16816(float* c, const unsigned* a, unsigned b0, unsigned b1) {
    asm volatile("mma.sync.aligned.m16n8k16.row.col.f32.bf16.bf16.f32 "
                 "{%0,%1,%2,%3}, {%4,%5,%6,%7}, {%8,%9}, {%0,%1,%2,%3};"
                 : "+f"(c[0]), "+f"(c[1]), "+f"(c[2]), "+f"(c[3])
                 : "r"(a[0]), "r"(a[1]), "r"(a[2]), "r"(a[3]), "r"(b0), "r"(b1));
}

// invert linear pair index p -> (i, j), i<j, over F=32 fields
__device__ __forceinline__ void decode_pair(int p, int& io, int& jo) {
    float s = sqrtf((float)(3969 - 8 * p));
    int i = (int)((63.0f - s) * 0.5f);
    while (((i + 1) * (2 * FNUM - i - 2)) / 2 <= p) ++i;   // start(i+1) <= p
    while ((i * (2 * FNUM - i - 1)) / 2 > p) --i;           // start(i) > p
    io = i;
    jo = p - (i * (2 * FNUM - i - 1)) / 2 + i + 1;
}

__global__ void __launch_bounds__(128)
afm_kernel(const int* __restrict__ x, const float* __restrict__ emb,
           const float* __restrict__ at_w, const float* __restrict__ at_b,
           const float* __restrict__ at_h, const float* __restrict__ pvec,
           const float* __restrict__ w0, const float* __restrict__ w1,
           float* __restrict__ out)
{
    __shared__ __align__(16) float          Vsh[FNUM][VROW];
    __shared__ __align__(16) __nv_bfloat16  Wt[NW][WROW];
    __shared__ float2         bh[HD];       // {at_b[h], at_h[h]}
    __shared__ float          warpsum[4];
    __shared__ float          fm1sh;
    __shared__ int            xsh[FNUM];

    const int tid = threadIdx.x;
    const int b   = blockIdx.x;

    // --- fm1 (first-order FM) + stage x indices ---
    if (tid < FNUM) {
        int xv = x[tid * BATCH + b];
        xsh[tid] = xv;
        float v = w1[xv];
        #pragma unroll
        for (int o = 16; o; o >>= 1) v += __shfl_xor_sync(0xffffffffu, v, o);
        if (tid == 0) fm1sh = v;
    }
    if (tid < HD) bh[tid] = make_float2(at_b[tid], at_h[tid]);
    __syncthreads();   // xsh visible

    // --- load V[f, :] rows (fp32) ---
    for (int idx = tid; idx < FNUM * (KD / 4); idx += 128) {
        int f = idx >> 4, q = idx & 15;
        float4 v4 = *reinterpret_cast<const float4*>(emb + (size_t)xsh[f] * KD + q * 4);
        *reinterpret_cast<float4*>(&Vsh[f][q * 4]) = v4;
    }
    // --- load W'^T: Wt[n][k] = at_w[k][n] for n<64, p[k] at n=64, zeros n=65..71 ---
    for (int idx = tid; idx < NW * KD; idx += 128) {
        int n = idx >> 6, k = idx & 63;
        float v = (n < HD) ? at_w[k * HD + n] : (n == HD ? pvec[k] : 0.0f);
        Wt[n][k] = __float2bfloat16(v);
    }
    __syncthreads();

    const int lane = tid & 31;
    const int warp = tid >> 5;
    const int quad = lane >> 2;          // C/A fragment row group (0..7)
    const int klo  = (lane & 3) * 2;     // fragment column pair base

    // hoist per-thread (bias, at_h) for the 16 columns this thread owns
    float2 bh0[8], bh1[8];
    #pragma unroll
    for (int nt = 0; nt < 8; nt++) {
        int cb = nt * 8 + klo;
        bh0[nt] = bh[cb];
        bh1[nt] = bh[cb + 1];
    }

    const unsigned wt_base =
        smem_u32(&Wt[lane & 7][(lane >> 3) * 8]);   // ldmatrix lane addressing

    float att = 0.0f;

    for (int c = warp; c < 31; c += 4) {           // 31 chunks of 16 pairs = 496
        int plo = c * 16 + quad;
        int phi = plo + 8;
        int i0, j0, i1, j1;
        decode_pair(plo, i0, j0);
        decode_pair(phi, i1, j1);
        const float* Vi0 = Vsh[i0];
        const float* Vj0 = Vsh[j0];
        const float* Vi1 = Vsh[i1];
        const float* Vj1 = Vsh[j1];

        // --- build A fragments (VV products) directly in registers ---
        unsigned A[4][4];
        #pragma unroll
        for (int kc = 0; kc < 4; kc++) {
            int k0 = kc * 16 + klo;
            float2 a, bb;
            a = *(const float2*)(Vi0 + k0);      bb = *(const float2*)(Vj0 + k0);
            A[kc][0] = cvt_bf16x2(a.y * bb.y, a.x * bb.x);        // row lo, k lo
            a = *(const float2*)(Vi1 + k0);      bb = *(const float2*)(Vj1 + k0);
            A[kc][1] = cvt_bf16x2(a.y * bb.y, a.x * bb.x);        // row hi, k lo
            a = *(const float2*)(Vi0 + k0 + 8);  bb = *(const float2*)(Vj0 + k0 + 8);
            A[kc][2] = cvt_bf16x2(a.y * bb.y, a.x * bb.x);        // row lo, k hi
            a = *(const float2*)(Vi1 + k0 + 8);  bb = *(const float2*)(Vj1 + k0 + 8);
            A[kc][3] = cvt_bf16x2(a.y * bb.y, a.x * bb.x);        // row hi, k hi
        }

        float acc[9][4];
        #pragma unroll
        for (int nt = 0; nt < 9; nt++)
            #pragma unroll
            for (int e = 0; e < 4; e++) acc[nt][e] = 0.0f;

        // --- GEMM: [16 pairs, 64] @ [64, 72] ---
        #pragma unroll
        for (int nt = 0; nt < 9; nt++) {
            unsigned addr = wt_base + nt * 8 * WROW * 2;
            unsigned b0, b1, b2, b3, b4, b5, b6, b7;
            ldmatrix_x4(b0, b1, b2, b3, addr);           // k 0..31
            ldmatrix_x4(b4, b5, b6, b7, addr + 32 * 2);  // k 32..63
            mma16816(acc[nt], A[0], b0, b1);
            mma16816(acc[nt], A[1], b2, b3);
            mma16816(acc[nt], A[2], b4, b5);
            mma16816(acc[nt], A[3], b6, b7);
        }

        // --- epilogue: score[r] = sum_h relu(S+b)*at_h ;  g[r] = S[r][64] ---
        float slo = 0.0f, shi = 0.0f;
        #pragma unroll
        for (int nt = 0; nt < 8; nt++) {
            slo += fmaxf(acc[nt][0] + bh0[nt].x, 0.0f) * bh0[nt].y
                 + fmaxf(acc[nt][1] + bh1[nt].x, 0.0f) * bh1[nt].y;
            shi += fmaxf(acc[nt][2] + bh0[nt].x, 0.0f) * bh0[nt].y
                 + fmaxf(acc[nt][3] + bh1[nt].x, 0.0f) * bh1[nt].y;
        }
        slo += __shfl_xor_sync(0xffffffffu, slo, 1);
        slo += __shfl_xor_sync(0xffffffffu, slo, 2);
        shi += __shfl_xor_sync(0xffffffffu, shi, 1);
        shi += __shfl_xor_sync(0xffffffffu, shi, 2);
        if ((lane & 3) == 0)
            att += slo * acc[8][0] + shi * acc[8][2];   // col 64 = g (no bias/relu)
    }

    // --- reductions + sigmoid ---
    #pragma unroll
    for (int o = 16; o; o >>= 1) att += __shfl_xor_sync(0xffffffffu, att, o);
    if (lane == 0) warpsum[warp] = att;
    __syncthreads();
    if (tid == 0) {
        float logit = warpsum[0] + warpsum[1] + warpsum[2] + warpsum[3] + fm1sh + w0[0];
        out[b] = 1.0f / (1.0f + expf(-logit));
    }
}

extern "C" void kernel_launch(void* const* d_in, const int* in_sizes, int n_in,
                              void* d_out, int out_size) {
    const int*   x    = (const int*)d_in[0];
    const float* emb  = (const float*)d_in[1];
    const float* at_w = (const float*)d_in[2];
    const float* at_b = (const float*)d_in[3];
    const float* at_h = (const float*)d_in[4];
    const float* pvec = (const float*)d_in[5];
    const float* w0   = (const float*)d_in[6];
    const float* w1   = (const float*)d_in[7];
    float* out = (float*)d_out;
    afm_kernel<<<BATCH, 128>>>(x, emb, at_w, at_b, at_h, pvec, w0, w1, out);
}

// round 5
// speedup vs baseline: 1.3450x; 1.3450x over previous
#include <cuda_runtime.h>
#include <cuda_bf16.h>
#include <math.h>

#define FNUM  32
#define BATCH 2048
#define KD    64
#define HD    64
#define NPAIR 496
#define VROW  68     // padded V row stride (floats)
#define WROW  72     // padded Wt row stride (bf16)

__device__ __forceinline__ unsigned smem_u32(const void* p) {
    return (unsigned)__cvta_generic_to_shared(p);
}

__device__ __forceinline__ unsigned cvt_bf16x2(float hi, float lo) {
    unsigned r;
    asm("cvt.rn.bf16x2.f32 %0, %1, %2;" : "=r"(r) : "f"(hi), "f"(lo));
    return r;
}

__device__ __forceinline__ void ldmatrix_x4(unsigned& r0, unsigned& r1, unsigned& r2, unsigned& r3,
                                            unsigned addr) {
    asm volatile("ldmatrix.sync.aligned.m8n8.x4.shared.b16 {%0,%1,%2,%3}, [%4];"
                 : "=r"(r0), "=r"(r1), "=r"(r2), "=r"(r3) : "r"(addr));
}

__device__ __forceinline__ void mma16816(float* c, const unsigned* a, unsigned b0, unsigned b1) {
    asm volatile("mma.sync.aligned.m16n8k16.row.col.f32.bf16.bf16.f32 "
                 "{%0,%1,%2,%3}, {%4,%5,%6,%7}, {%8,%9}, {%0,%1,%2,%3};"
                 : "+f"(c[0]), "+f"(c[1]), "+f"(c[2]), "+f"(c[3])
                 : "r"(a[0]), "r"(a[1]), "r"(a[2]), "r"(a[3]), "r"(b0), "r"(b1));
}

// invert linear pair index p -> (i, j), i<j, over F=32 fields
__device__ __forceinline__ void decode_pair(int p, int& io, int& jo) {
    float s = sqrtf((float)(3969 - 8 * p));
    int i = (int)((63.0f - s) * 0.5f);
    while (((i + 1) * (2 * FNUM - i - 2)) / 2 <= p) ++i;
    while ((i * (2 * FNUM - i - 1)) / 2 > p) --i;
    io = i;
    jo = p - (i * (2 * FNUM - i - 1)) / 2 + i + 1;
}

__global__ void __launch_bounds__(128)
afm_kernel(const int* __restrict__ x, const float* __restrict__ emb,
           const float* __restrict__ at_w, const float* __restrict__ at_b,
           const float* __restrict__ at_h, const float* __restrict__ pvec,
           const float* __restrict__ w0, const float* __restrict__ w1,
           float* __restrict__ out)
{
    __shared__ __align__(16) float          Vsh[2][FNUM][VROW];
    __shared__ __align__(16) __nv_bfloat16  Wt[HD][WROW];
    __shared__ float2          bhsh[HD];     // {at_b[h], at_h[h]}
    __shared__ float           psh[KD];
    __shared__ unsigned short  pairsh[NPAIR];
    __shared__ float           warpsum[2][4];
    __shared__ float           fm1sh[2];
    __shared__ int             xsh[2][FNUM];

    const int tid = threadIdx.x;
    const int b0  = blockIdx.x * 2;

    // --- fm1 (first-order FM) + stage x indices, 2 batches ---
    if (tid < 64) {
        int bb = tid >> 5, f = tid & 31;
        int xv = x[f * BATCH + b0 + bb];
        xsh[bb][f] = xv;
        float v = w1[xv];
        #pragma unroll
        for (int o = 16; o; o >>= 1) v += __shfl_xor_sync(0xffffffffu, v, o);
        if (f == 0) fm1sh[bb] = v;
    }
    if (tid < HD) {
        bhsh[tid] = make_float2(at_b[tid], at_h[tid]);
        psh[tid]  = pvec[tid];
    }
    // --- pair (i,j) LUT ---
    for (int pp = tid; pp < NPAIR; pp += 128) {
        int i, j;
        decode_pair(pp, i, j);
        pairsh[pp] = (unsigned short)((i << 8) | j);
    }
    __syncthreads();   // xsh visible

    // --- load V rows (fp32), both batches ---
    for (int idx = tid; idx < 2 * FNUM * (KD / 4); idx += 128) {
        int bb = idx >> 9, f = (idx >> 4) & 31, q = idx & 15;
        float4 v4 = *reinterpret_cast<const float4*>(emb + (size_t)xsh[bb][f] * KD + q * 4);
        *reinterpret_cast<float4*>(&Vsh[bb][f][q * 4]) = v4;
    }
    // --- load W^T: Wt[n][k] = at_w[k][n] ---
    for (int idx = tid; idx < HD * KD; idx += 128) {
        int n = idx >> 6, k = idx & 63;
        Wt[n][k] = __float2bfloat16(at_w[k * HD + n]);
    }
    __syncthreads();

    const int lane = tid & 31;
    const int warp = tid >> 5;
    const int quad = lane >> 2;          // fragment row group (0..7)
    const int klo  = (lane & 3) * 2;     // fragment column pair base

    // per-thread (bias, at_h) for owned columns
    float2 bh0[8], bh1[8];
    #pragma unroll
    for (int nt = 0; nt < 8; nt++) {
        int cb = nt * 8 + klo;
        bh0[nt] = bhsh[cb];
        bh1[nt] = bhsh[cb + 1];
    }
    // per-thread p[k] values for the 16 k-slots this thread owns
    float2 pA[4], pB[4];
    #pragma unroll
    for (int kc = 0; kc < 4; kc++) {
        int k0 = kc * 16 + klo;
        pA[kc] = make_float2(psh[k0],     psh[k0 + 1]);
        pB[kc] = make_float2(psh[k0 + 8], psh[k0 + 9]);
    }

    // --- hoist ALL B fragments (loop-invariant W) into registers ---
    const unsigned wt_base = smem_u32(&Wt[lane & 7][(lane >> 3) * 8]);
    unsigned Bf[8][8];
    #pragma unroll
    for (int nt = 0; nt < 8; nt++) {
        unsigned addr = wt_base + nt * 8 * WROW * 2;
        ldmatrix_x4(Bf[nt][0], Bf[nt][1], Bf[nt][2], Bf[nt][3], addr);
        ldmatrix_x4(Bf[nt][4], Bf[nt][5], Bf[nt][6], Bf[nt][7], addr + 32 * 2);
    }

    for (int bb = 0; bb < 2; bb++) {
        float att = 0.0f;

        for (int c = warp; c < 31; c += 4) {       // 31 chunks of 16 pairs
            int plo = c * 16 + quad;
            unsigned pl = pairsh[plo], ph = pairsh[plo + 8];
            const float* Vi0 = Vsh[bb][pl >> 8];
            const float* Vj0 = Vsh[bb][pl & 255];
            const float* Vi1 = Vsh[bb][ph >> 8];
            const float* Vj1 = Vsh[bb][ph & 255];

            // A fragments (VV in bf16) + fp32 g = VV . p on the fly
            unsigned A[4][4];
            float glo = 0.0f, ghi = 0.0f;
            #pragma unroll
            for (int kc = 0; kc < 4; kc++) {
                int k0 = kc * 16 + klo;
                float2 a, v;
                float x0, x1;
                a = *(const float2*)(Vi0 + k0);     v = *(const float2*)(Vj0 + k0);
                x0 = a.x * v.x; x1 = a.y * v.y;
                A[kc][0] = cvt_bf16x2(x1, x0);
                glo = fmaf(x0, pA[kc].x, fmaf(x1, pA[kc].y, glo));
                a = *(const float2*)(Vi1 + k0);     v = *(const float2*)(Vj1 + k0);
                x0 = a.x * v.x; x1 = a.y * v.y;
                A[kc][1] = cvt_bf16x2(x1, x0);
                ghi = fmaf(x0, pA[kc].x, fmaf(x1, pA[kc].y, ghi));
                a = *(const float2*)(Vi0 + k0 + 8); v = *(const float2*)(Vj0 + k0 + 8);
                x0 = a.x * v.x; x1 = a.y * v.y;
                A[kc][2] = cvt_bf16x2(x1, x0);
                glo = fmaf(x0, pB[kc].x, fmaf(x1, pB[kc].y, glo));
                a = *(const float2*)(Vi1 + k0 + 8); v = *(const float2*)(Vj1 + k0 + 8);
                x0 = a.x * v.x; x1 = a.y * v.y;
                A[kc][3] = cvt_bf16x2(x1, x0);
                ghi = fmaf(x0, pB[kc].x, fmaf(x1, pB[kc].y, ghi));
            }

            // GEMM [16,64]@[64,64] with fused per-nt epilogue (acc stays at 8 regs)
            float slo = 0.0f, shi = 0.0f;
            #pragma unroll
            for (int nt = 0; nt < 8; nt += 2) {
                float acc0[4] = {0.f, 0.f, 0.f, 0.f};
                float acc1[4] = {0.f, 0.f, 0.f, 0.f};
                mma16816(acc0, A[0], Bf[nt][0], Bf[nt][1]);
                mma16816(acc0, A[1], Bf[nt][2], Bf[nt][3]);
                mma16816(acc0, A[2], Bf[nt][4], Bf[nt][5]);
                mma16816(acc0, A[3], Bf[nt][6], Bf[nt][7]);
                mma16816(acc1, A[0], Bf[nt + 1][0], Bf[nt + 1][1]);
                mma16816(acc1, A[1], Bf[nt + 1][2], Bf[nt + 1][3]);
                mma16816(acc1, A[2], Bf[nt + 1][4], Bf[nt + 1][5]);
                mma16816(acc1, A[3], Bf[nt + 1][6], Bf[nt + 1][7]);
                slo += fmaxf(acc0[0] + bh0[nt].x,     0.0f) * bh0[nt].y
                     + fmaxf(acc0[1] + bh1[nt].x,     0.0f) * bh1[nt].y
                     + fmaxf(acc1[0] + bh0[nt + 1].x, 0.0f) * bh0[nt + 1].y
                     + fmaxf(acc1[1] + bh1[nt + 1].x, 0.0f) * bh1[nt + 1].y;
                shi += fmaxf(acc0[2] + bh0[nt].x,     0.0f) * bh0[nt].y
                     + fmaxf(acc0[3] + bh1[nt].x,     0.0f) * bh1[nt].y
                     + fmaxf(acc1[2] + bh0[nt + 1].x, 0.0f) * bh0[nt + 1].y
                     + fmaxf(acc1[3] + bh1[nt + 1].x, 0.0f) * bh1[nt + 1].y;
            }

            // reduce score and g over the quad (n / k slots)
            slo += __shfl_xor_sync(0xffffffffu, slo, 1);
            slo += __shfl_xor_sync(0xffffffffu, slo, 2);
            shi += __shfl_xor_sync(0xffffffffu, shi, 1);
            shi += __shfl_xor_sync(0xffffffffu, shi, 2);
            glo += __shfl_xor_sync(0xffffffffu, glo, 1);
            glo += __shfl_xor_sync(0xffffffffu, glo, 2);
            ghi += __shfl_xor_sync(0xffffffffu, ghi, 1);
            ghi += __shfl_xor_sync(0xffffffffu, ghi, 2);
            if ((lane & 3) == 0) att += slo * glo + shi * ghi;
        }

        #pragma unroll
        for (int o = 16; o; o >>= 1) att += __shfl_xor_sync(0xffffffffu, att, o);
        if (lane == 0) warpsum[bb][warp] = att;
    }

    __syncthreads();
    if (tid < 2) {
        float logit = warpsum[tid][0] + warpsum[tid][1] + warpsum[tid][2] + warpsum[tid][3]
                    + fm1sh[tid] + w0[0];
        out[b0 + tid] = 1.0f / (1.0f + expf(-logit));
    }
}

extern "C" void kernel_launch(void* const* d_in, const int* in_sizes, int n_in,
                              void* d_out, int out_size) {
    const int*   x    = (const int*)d_in[0];
    const float* emb  = (const float*)d_in[1];
    const float* at_w = (const float*)d_in[2];
    const float* at_b = (const float*)d_in[3];
    const float* at_h = (const float*)d_in[4];
    const float* pvec = (const float*)d_in[5];
    const float* w0   = (const float*)d_in[6];
    const float* w1   = (const float*)d_in[7];
    float* out = (float*)d_out;
    afm_kernel<<<BATCH / 2, 128>>>(x, emb, at_w, at_b, at_h, pvec, w0, w1, out);
}

// round 10
// speedup vs baseline: 1.7104x; 1.2717x over previous
#include <cuda_runtime.h>
#include <cuda_bf16.h>
#include <math.h>

#define FNUM  32
#define BATCH 2048
#define KD    64
#define HD    64
#define NPAIR 496
#define WROW  72     // Wt row stride (bf16)

__device__ __forceinline__ unsigned cvt_bf16x2(float hi, float lo) {
    unsigned r;
    asm("cvt.rn.bf16x2.f32 %0, %1, %2;" : "=r"(r) : "f"(hi), "f"(lo));
    return r;
}

__device__ __forceinline__ unsigned hmul2u(unsigned a, unsigned b) {
    unsigned r;
    asm("mul.rn.bf16x2 %0, %1, %2;" : "=r"(r) : "r"(a), "r"(b));
    return r;
}

__device__ __forceinline__ void mma16816(float* c, const unsigned* a, unsigned b0, unsigned b1) {
    asm volatile("mma.sync.aligned.m16n8k16.row.col.f32.bf16.bf16.f32 "
                 "{%0,%1,%2,%3}, {%4,%5,%6,%7}, {%8,%9}, {%0,%1,%2,%3};"
                 : "+f"(c[0]), "+f"(c[1]), "+f"(c[2]), "+f"(c[3])
                 : "r"(a[0]), "r"(a[1]), "r"(a[2]), "r"(a[3]), "r"(b0), "r"(b1));
}

// invert linear pair index p -> (i, j), i<j, over F=32 fields
__device__ __forceinline__ void decode_pair(int p, int& io, int& jo) {
    float s = sqrtf((float)(3969 - 8 * p));
    int i = (int)((63.0f - s) * 0.5f);
    while (((i + 1) * (2 * FNUM - i - 2)) / 2 <= p) ++i;
    while ((i * (2 * FNUM - i - 1)) / 2 > p) --i;
    io = i;
    jo = p - (i * (2 * FNUM - i - 1)) / 2 + i + 1;
}

// physical placement of logical bf16x2-pair m (=k/2, 0..31):
//   kc=m>>3, r=m&7, q=r&3, hi=r>>2  ->  phys uint index q*8 + kc*2 + hi
// so thread q owns phys uints [8q, 8q+8) = two contiguous uint4 (16B segs 2q, 2q+1).
// 16B segments are XOR-swizzled by (field & 7) for bank-conflict freedom.
__device__ __forceinline__ int vperm_idx(int m, int f) {
    int kc = m >> 3, r = m & 7, q = r & 3, hi = r >> 2;
    int pu = q * 8 + kc * 2 + hi;
    return ((((pu >> 2) ^ (f & 7)) << 2)) | (pu & 3);
}

__global__ void __launch_bounds__(128)
afm_kernel(const int* __restrict__ x, const float* __restrict__ emb,
           const float* __restrict__ at_w, const float* __restrict__ at_b,
           const float* __restrict__ at_h, const float* __restrict__ pvec,
           const float* __restrict__ w0, const float* __restrict__ w1,
           float* __restrict__ out)
{
    __shared__ __align__(16) unsigned       Vb[2][FNUM][32];   // bf16x2, permuted+swizzled
    __shared__ __align__(16) __nv_bfloat16  Wt[HD][WROW];      // Wt[n][k] = at_w[k][n]
    __shared__ float2          bhsh[HD];     // {at_b[h], at_h[h]}
    __shared__ float           psh[KD];
    __shared__ unsigned short  pairsh[NPAIR];
    __shared__ float           warpsum[2][4];
    __shared__ float           fm1sh[2];
    __shared__ int             xsh[2][FNUM];

    const int tid = threadIdx.x;
    const int b0  = blockIdx.x * 2;

    // --- fm1 + stage x indices, 2 batches ---
    if (tid < 64) {
        int bb = tid >> 5, f = tid & 31;
        int xv = x[f * BATCH + b0 + bb];
        xsh[bb][f] = xv;
        float v = w1[xv];
        #pragma unroll
        for (int o = 16; o; o >>= 1) v += __shfl_xor_sync(0xffffffffu, v, o);
        if (f == 0) fm1sh[bb] = v;
    }
    if (tid < HD) {
        bhsh[tid] = make_float2(at_b[tid], at_h[tid]);
        psh[tid]  = pvec[tid];
    }
    for (int pp = tid; pp < NPAIR; pp += 128) {
        int i, j;
        decode_pair(pp, i, j);
        pairsh[pp] = (unsigned short)((i << 8) | j);
    }
    __syncthreads();   // xsh visible

    // --- load V rows (fp32 gmem -> bf16x2 permuted smem), 64 rows, 2 threads/row ---
    {
        int row = tid >> 1, half = tid & 1;     // half: logical k 0..31 / 32..63
        int bb = row >> 5, f = row & 31;
        const float4* src = reinterpret_cast<const float4*>(emb + (size_t)xsh[bb][f] * KD) + half * 8;
        unsigned* dst = Vb[bb][f];
        #pragma unroll
        for (int u = 0; u < 8; u++) {
            float4 v4 = src[u];
            int m = half * 16 + 2 * u;
            dst[vperm_idx(m, f)]     = cvt_bf16x2(v4.y, v4.x);
            dst[vperm_idx(m + 1, f)] = cvt_bf16x2(v4.w, v4.z);
        }
    }
    // --- load W^T ---
    for (int idx = tid; idx < HD * KD; idx += 128) {
        int n = idx >> 6, k = idx & 63;
        Wt[n][k] = __float2bfloat16(at_w[k * HD + n]);
    }
    __syncthreads();

    const int lane = tid & 31;
    const int warp = tid >> 5;
    const int quad = lane >> 2;          // fragment row group (0..7)
    const int q    = lane & 3;           // fragment k/n sub-lane

    // per-thread (bias, at_h) for owned C columns: n = nt*8 + 2q + {0,1}
    float2 bh0[8], bh1[8];
    #pragma unroll
    for (int nt = 0; nt < 8; nt++) {
        int cb = nt * 8 + q * 2;
        bh0[nt] = bhsh[cb];
        bh1[nt] = bhsh[cb + 1];
    }

    // --- build all B fragments once by plain loads (logical k-order) ---
    unsigned Bf[8][8];
    #pragma unroll
    for (int nt = 0; nt < 8; nt++) {
        const __nv_bfloat16* wr = Wt[nt * 8 + quad];
        #pragma unroll
        for (int kc = 0; kc < 4; kc++) {
            Bf[nt][2 * kc]     = *reinterpret_cast<const unsigned*>(wr + 16 * kc + 2 * q);
            Bf[nt][2 * kc + 1] = *reinterpret_cast<const unsigned*>(wr + 16 * kc + 2 * q + 8);
        }
    }
    // --- p-vector B fragment (column 0 only: quad 0 lanes carry p, rest zero) ---
    unsigned pb0[4], pb1[4];
    #pragma unroll
    for (int kc = 0; kc < 4; kc++) {
        if (quad == 0) {
            pb0[kc] = cvt_bf16x2(psh[16 * kc + 2 * q + 1], psh[16 * kc + 2 * q]);
            pb1[kc] = cvt_bf16x2(psh[16 * kc + 2 * q + 9], psh[16 * kc + 2 * q + 8]);
        } else { pb0[kc] = 0u; pb1[kc] = 0u; }
    }

    for (int bb = 0; bb < 2; bb++) {
        float att = 0.0f;

        for (int c = warp; c < 31; c += 4) {       // 31 chunks of 16 pairs
            int plo = c * 16 + quad;
            unsigned pl = pairsh[plo], ph = pairsh[plo + 8];
            int fi0 = pl >> 8, fj0 = pl & 255;
            int fi1 = ph >> 8, fj1 = ph & 255;

            const uint4* Ri0 = reinterpret_cast<const uint4*>(Vb[bb][fi0]);
            const uint4* Rj0 = reinterpret_cast<const uint4*>(Vb[bb][fj0]);
            const uint4* Ri1 = reinterpret_cast<const uint4*>(Vb[bb][fi1]);
            const uint4* Rj1 = reinterpret_cast<const uint4*>(Vb[bb][fj1]);
            int s0 = 2 * q, s1 = 2 * q + 1;
            uint4 i0a = Ri0[s0 ^ (fi0 & 7)], i0b = Ri0[s1 ^ (fi0 & 7)];
            uint4 j0a = Rj0[s0 ^ (fj0 & 7)], j0b = Rj0[s1 ^ (fj0 & 7)];
            uint4 i1a = Ri1[s0 ^ (fi1 & 7)], i1b = Ri1[s1 ^ (fi1 & 7)];
            uint4 j1a = Rj1[s0 ^ (fj1 & 7)], j1b = Rj1[s1 ^ (fj1 & 7)];

            // A fragments: VV in bf16 via packed multiplies
            unsigned A[4][4];
            A[0][0] = hmul2u(i0a.x, j0a.x);  A[0][2] = hmul2u(i0a.y, j0a.y);
            A[1][0] = hmul2u(i0a.z, j0a.z);  A[1][2] = hmul2u(i0a.w, j0a.w);
            A[2][0] = hmul2u(i0b.x, j0b.x);  A[2][2] = hmul2u(i0b.y, j0b.y);
            A[3][0] = hmul2u(i0b.z, j0b.z);  A[3][2] = hmul2u(i0b.w, j0b.w);
            A[0][1] = hmul2u(i1a.x, j1a.x);  A[0][3] = hmul2u(i1a.y, j1a.y);
            A[1][1] = hmul2u(i1a.z, j1a.z);  A[1][3] = hmul2u(i1a.w, j1a.w);
            A[2][1] = hmul2u(i1b.x, j1b.x);  A[2][3] = hmul2u(i1b.y, j1b.y);
            A[3][1] = hmul2u(i1b.z, j1b.z);  A[3][3] = hmul2u(i1b.w, j1b.w);

            // g = VV . p via MMA into column 0
            float accg[4] = {0.f, 0.f, 0.f, 0.f};
            mma16816(accg, A[0], pb0[0], pb1[0]);
            mma16816(accg, A[1], pb0[1], pb1[1]);
            mma16816(accg, A[2], pb0[2], pb1[2]);
            mma16816(accg, A[3], pb0[3], pb1[3]);

            // hid GEMM with fused per-nt epilogue
            float slo = 0.0f, shi = 0.0f;
            #pragma unroll
            for (int nt = 0; nt < 8; nt += 2) {
                float acc0[4] = {0.f, 0.f, 0.f, 0.f};
                float acc1[4] = {0.f, 0.f, 0.f, 0.f};
                mma16816(acc0, A[0], Bf[nt][0], Bf[nt][1]);
                mma16816(acc0, A[1], Bf[nt][2], Bf[nt][3]);
                mma16816(acc0, A[2], Bf[nt][4], Bf[nt][5]);
                mma16816(acc0, A[3], Bf[nt][6], Bf[nt][7]);
                mma16816(acc1, A[0], Bf[nt + 1][0], Bf[nt + 1][1]);
                mma16816(acc1, A[1], Bf[nt + 1][2], Bf[nt + 1][3]);
                mma16816(acc1, A[2], Bf[nt + 1][4], Bf[nt + 1][5]);
                mma16816(acc1, A[3], Bf[nt + 1][6], Bf[nt + 1][7]);
                slo += fmaxf(acc0[0] + bh0[nt].x,     0.0f) * bh0[nt].y
                     + fmaxf(acc0[1] + bh1[nt].x,     0.0f) * bh1[nt].y
                     + fmaxf(acc1[0] + bh0[nt + 1].x, 0.0f) * bh0[nt + 1].y
                     + fmaxf(acc1[1] + bh1[nt + 1].x, 0.0f) * bh1[nt + 1].y;
                shi += fmaxf(acc0[2] + bh0[nt].x,     0.0f) * bh0[nt].y
                     + fmaxf(acc0[3] + bh1[nt].x,     0.0f) * bh1[nt].y
                     + fmaxf(acc1[2] + bh0[nt + 1].x, 0.0f) * bh0[nt + 1].y
                     + fmaxf(acc1[3] + bh1[nt + 1].x, 0.0f) * bh1[nt + 1].y;
            }

            // reduce score over the 4 n-sublanes; g is already complete at q==0
            slo += __shfl_xor_sync(0xffffffffu, slo, 1);
            slo += __shfl_xor_sync(0xffffffffu, slo, 2);
            shi += __shfl_xor_sync(0xffffffffu, shi, 1);
            shi += __shfl_xor_sync(0xffffffffu, shi, 2);
            if (q == 0) att += slo * accg[0] + shi * accg[2];
        }

        #pragma unroll
        for (int o = 16; o; o >>= 1) att += __shfl_xor_sync(0xffffffffu, att, o);
        if (lane == 0) warpsum[bb][warp] = att;
    }

    __syncthreads();
    if (tid < 2) {
        float logit = warpsum[tid][0] + warpsum[tid][1] + warpsum[tid][2] + warpsum[tid][3]
                    + fm1sh[tid] + w0[0];
        out[b0 + tid] = 1.0f / (1.0f + expf(-logit));
    }
}

extern "C" void kernel_launch(void* const* d_in, const int* in_sizes, int n_in,
                              void* d_out, int out_size) {
    const int*   x    = (const int*)d_in[0];
    const float* emb  = (const float*)d_in[1];
    const float* at_w = (const float*)d_in[2];
    const float* at_b = (const float*)d_in[3];
    const float* at_h = (const float*)d_in[4];
    const float* pvec = (const float*)d_in[5];
    const float* w0   = (const float*)d_in[6];
    const float* w1   = (const float*)d_in[7];
    float* out = (float*)d_out;
    afm_kernel<<<BATCH / 2, 128>>>(x, emb, at_w, at_b, at_h, pvec, w0, w1, out);
}